// round 16
// baseline (speedup 1.0000x reference)
#include <cuda_runtime.h>
#include <cuda_fp16.h>
#include <cstdint>

#define BATCH 1024
#define SEQT  256
#define DIN   128
#define HID   512
#define ZD    64
#define G4    2048   // 4*HID

// ---------------- packed fp16 operand buffers (mma.m16n8k16 fragment order) ----------------
// Weights: [hb(16)][kc(40)][wn(4)][gp(2)][lane(32)][8 halves]
__device__ __half g_wp[16 * 40 * 4 * 2 * 32 * 8];          // 2.62 MB
// x: [mb(8)][t(256)][kc(8)][mtile(8)][lane(32)][8 halves]
__device__ __half g_xp[8 * 256 * 8 * 8 * 32 * 8];          // 67 MB
// h ping-pong: [buf(2)][mb(8)][kc(32)][mtile(8)][lane(32)][8 halves]
__device__ __half g_hp[2 * 8 * 32 * 8 * 32 * 8];           // 2 MB
// per-mb barrier state (128B stride)
__device__ unsigned          g_bcnt[8 * 32];
__device__ volatile unsigned g_bgen[8 * 32];

__device__ __forceinline__ float sigmoidf_(float v) {
    return 1.0f / (1.0f + __expf(-v));
}
__device__ __forceinline__ float softplusf_(float v) {
    return (v > 20.0f) ? v : log1pf(__expf(v));
}
__device__ __forceinline__ void mma_f16(float c[4], const uint4& a, uint32_t b0, uint32_t b1) {
    asm volatile(
        "mma.sync.aligned.m16n8k16.row.col.f32.f16.f16.f32 "
        "{%0,%1,%2,%3}, {%4,%5,%6,%7}, {%8,%9}, {%0,%1,%2,%3};"
        : "+f"(c[0]), "+f"(c[1]), "+f"(c[2]), "+f"(c[3])
        : "r"(a.x), "r"(a.y), "r"(a.z), "r"(a.w), "r"(b0), "r"(b1));
}
__device__ __forceinline__ uint4 ldg_cg_128(const void* p) {
    uint4 v;
    asm volatile("ld.global.cg.v4.u32 {%0,%1,%2,%3}, [%4];"
                 : "=r"(v.x), "=r"(v.y), "=r"(v.z), "=r"(v.w) : "l"(p));
    return v;
}
__device__ __forceinline__ uint32_t h2_bits(__half2 h) {
    uint32_t u;
    memcpy(&u, &h, 4);
    return u;
}

constexpr int SMEM_BYTES = 40 * 4096;   // 160 KB: B slice [kc40][wn4][gp2][lane32][16B]

// ---- persistent kernel: grid (16 hb, 8 mb), 512 threads = 16 warps (4 wm x 4 wn)
// (byte-identical to the R12/R15 best mainloop)
__global__ __launch_bounds__(512, 1) void lstm_persist_kernel(const float* __restrict__ bias)
{
    extern __shared__ char sB[];
    const int hb  = blockIdx.x;
    const int mb  = blockIdx.y;
    const int tid = threadIdx.x;
    const int wid = tid >> 5;
    const int lane = tid & 31;
    const int wn = wid & 3;
    const int wm = wid >> 2;      // 0..3 -> mtiles {2wm, 2wm+1}
    const int qid = lane >> 2;
    const int qtr = lane & 3;

    // load persistent B slice into smem (once)
    {
        const uint4* src = reinterpret_cast<const uint4*>(g_wp) + (size_t)hb * (SMEM_BYTES / 16);
        uint4* dst = reinterpret_cast<uint4*>(sB);
        for (int i = tid; i < SMEM_BYTES / 16; i += 512) dst[i] = src[i];
    }
    float bs[4][2];
#pragma unroll
    for (int g = 0; g < 4; g++)
#pragma unroll
        for (int u = 0; u < 2; u++)
            bs[g][u] = bias[g * HID + hb * 32 + wn * 8 + qtr * 2 + u];

    float creg[2][2][2];
#pragma unroll
    for (int mt = 0; mt < 2; mt++)
#pragma unroll
        for (int h = 0; h < 2; h++)
#pragma unroll
            for (int u = 0; u < 2; u++)
                creg[mt][h][u] = 0.0f;

    float acc[2][4][4];

    auto zero_acc = [&]() {
#pragma unroll
        for (int mt = 0; mt < 2; mt++)
#pragma unroll
            for (int g = 0; g < 4; g++)
#pragma unroll
                for (int q = 0; q < 4; q++)
                    acc[mt][g][q] = 0.0f;
    };
    auto x_mma = [&](int tt) {
        const uint4* ax = reinterpret_cast<const uint4*>(
            g_xp + ((size_t)(mb * 256 + tt) * 8) * 2048);
#pragma unroll
        for (int kc = 0; kc < 8; kc++) {
            uint4 a0 = ax[(size_t)kc * 256 + (wm * 2 + 0) * 32 + lane];
            uint4 a1 = ax[(size_t)kc * 256 + (wm * 2 + 1) * 32 + lane];
            const uint4* bp = reinterpret_cast<const uint4*>(
                sB + kc * 4096 + (wn * 2) * 512 + lane * 16);
            uint4 b0 = bp[0];
            uint4 b1 = bp[32];
            mma_f16(acc[0][0], a0, b0.x, b0.y);
            mma_f16(acc[0][1], a0, b0.z, b0.w);
            mma_f16(acc[0][2], a0, b1.x, b1.y);
            mma_f16(acc[0][3], a0, b1.z, b1.w);
            mma_f16(acc[1][0], a1, b0.x, b0.y);
            mma_f16(acc[1][1], a1, b0.z, b0.w);
            mma_f16(acc[1][2], a1, b1.x, b1.y);
            mma_f16(acc[1][3], a1, b1.z, b1.w);
        }
    };

    __syncthreads();
    unsigned gen = g_bgen[mb * 32];

    const int kc_h  = hb * 2 + (wn >> 1);
    const int khalf = wn & 1;

    // prologue: x part of t=0 (h0 = 0)
    zero_acc();
    x_mma(0);

    for (int t = 0; t < SEQT; t++) {
        // ---- h chunks (kc 8..39): L2 loads
        if (t > 0) {
            const __half* ah = g_hp + ((size_t)((t & 1) * 8 + mb) * 32) * 2048;
#pragma unroll 8
            for (int kc = 0; kc < 32; kc++) {
                uint4 a0 = ldg_cg_128(ah + ((size_t)kc * 8 + wm * 2 + 0) * 256 + lane * 8);
                uint4 a1 = ldg_cg_128(ah + ((size_t)kc * 8 + wm * 2 + 1) * 256 + lane * 8);
                const uint4* bp = reinterpret_cast<const uint4*>(
                    sB + (kc + 8) * 4096 + (wn * 2) * 512 + lane * 16);
                uint4 b0 = bp[0];
                uint4 b1 = bp[32];
                mma_f16(acc[0][0], a0, b0.x, b0.y);
                mma_f16(acc[0][1], a0, b0.z, b0.w);
                mma_f16(acc[0][2], a0, b1.x, b1.y);
                mma_f16(acc[0][3], a0, b1.z, b1.w);
                mma_f16(acc[1][0], a1, b0.x, b0.y);
                mma_f16(acc[1][1], a1, b0.z, b0.w);
                mma_f16(acc[1][2], a1, b1.x, b1.y);
                mma_f16(acc[1][3], a1, b1.z, b1.w);
            }
        }

        // ---- LSTM epilogue: c in regs, h(t+1) written as packed fragments
        const int hbuf = (t + 1) & 1;
#pragma unroll
        for (int mt = 0; mt < 2; mt++) {
            float res[2][2];
#pragma unroll
            for (int half = 0; half < 2; half++) {
#pragma unroll
                for (int u = 0; u < 2; u++) {
                    int q = half * 2 + u;
                    float gi = acc[mt][0][q] + bs[0][u];
                    float gf = acc[mt][1][q] + bs[1][u];
                    float gg = acc[mt][2][q] + bs[2][u];
                    float go = acc[mt][3][q] + bs[3][u];
                    float iv = sigmoidf_(gi);
                    float fv = sigmoidf_(gf);
                    float gv = softplusf_(gg);
                    float ov = sigmoidf_(go);
                    float cn = fv * creg[mt][half][u] + iv * gv;
                    creg[mt][half][u] = cn;
                    res[half][u] = ov * softplusf_(cn);
                }
            }
            __half2 r0 = __floats2half2_rn(res[0][0], res[0][1]);
            __half2 r1 = __floats2half2_rn(res[1][0], res[1][1]);
            size_t off = (((size_t)(hbuf * 8 + mb) * 32 + kc_h) * 8 + (wm * 2 + mt)) * 256
                         + (size_t)(qid * 4 + qtr) * 8 + khalf * 4;
            uint2 val;
            val.x = h2_bits(r0);
            val.y = h2_bits(r1);
            *reinterpret_cast<uint2*>(g_hp + off) = val;
        }

        // ---- barrier with x-compute overlap
        if (t + 1 < SEQT) {
            __threadfence();
            __syncthreads();
            if (tid == 0) {
                unsigned ticket = atomicAdd(&g_bcnt[mb * 32], 1u);
                if (ticket == 15u) {
                    atomicExch(&g_bcnt[mb * 32], 0u);
                    __threadfence();
                    g_bgen[mb * 32] = gen + 1u;   // release immediately
                }
            }
            zero_acc();
            x_mma(t + 1);     // overlap: independent of other CTAs
            if (tid == 0) {
                while (g_bgen[mb * 32] == gen) __nanosleep(16);
            }
            __syncthreads();
            gen = gen + 1u;
            __threadfence();
        }
    }
}

// ---- pack weights into fp16 fragment order
__global__ void pack_w_kernel(const float* __restrict__ W, const float* __restrict__ U) {
    int idx = blockIdx.x * blockDim.x + threadIdx.x;
    if (idx >= 16 * 40 * 4 * 2 * 32) return;
    int lane = idx & 31;
    int gp   = (idx >> 5) & 1;
    int wn   = (idx >> 6) & 3;
    int rest = idx >> 8;
    int kc = rest % 40;
    int hb = rest / 40;
    int qid = lane >> 2, qtr = lane & 3;
    __half2 h2[4];
#pragma unroll
    for (int g2 = 0; g2 < 2; g2++) {
        int col = (gp * 2 + g2) * HID + hb * 32 + wn * 8 + qid;
#pragma unroll
        for (int hi = 0; hi < 2; hi++) {
            int k = kc * 16 + qtr * 2 + hi * 8;
            float v0 = (k     < DIN) ? W[(size_t)k * G4 + col]       : U[(size_t)(k - DIN) * G4 + col];
            float v1 = (k + 1 < DIN) ? W[(size_t)(k + 1) * G4 + col] : U[(size_t)(k + 1 - DIN) * G4 + col];
            h2[g2 * 2 + hi] = __floats2half2_rn(v0, v1);
        }
    }
    __half* dst = g_wp + ((((size_t)(hb * 40 + kc) * 4 + wn) * 2 + gp) * 32 + lane) * 8;
    *reinterpret_cast<uint4*>(dst) = *reinterpret_cast<uint4*>(h2);
}

// ---- pack x via smem staging: block per (t, mb)
__global__ __launch_bounds__(256) void pack_x_kernel(const float* __restrict__ x) {
    __shared__ __half s[128 * 136];
    const int t  = blockIdx.x;
    const int mb = blockIdx.y;
    const int tid = threadIdx.x;
    for (int i = tid; i < 128 * 32; i += 256) {
        int row = i >> 5, q4 = i & 31;
        const float4 v = *reinterpret_cast<const float4*>(
            x + ((size_t)(mb * 128 + row) * SEQT + t) * DIN + q4 * 4);
        __half2 lo = __floats2half2_rn(v.x, v.y);
        __half2 hi = __floats2half2_rn(v.z, v.w);
        __half* p = s + row * 136 + q4 * 4;
        *reinterpret_cast<__half2*>(p)     = lo;
        *reinterpret_cast<__half2*>(p + 2) = hi;
    }
    __syncthreads();
    for (int o = tid; o < 2048; o += 256) {
        int lane = o & 31, mtile = (o >> 5) & 7, kc = o >> 8;
        int qid = lane >> 2, qtr = lane & 3;
        int row0 = mtile * 16 + qid;
        int k0 = kc * 16 + qtr * 2;
        __half2 h2[4];
        h2[0] = *reinterpret_cast<const __half2*>(s + row0 * 136 + k0);
        h2[1] = *reinterpret_cast<const __half2*>(s + (row0 + 8) * 136 + k0);
        h2[2] = *reinterpret_cast<const __half2*>(s + row0 * 136 + k0 + 8);
        h2[3] = *reinterpret_cast<const __half2*>(s + (row0 + 8) * 136 + k0 + 8);
        __half* dst = g_xp + ((((size_t)(mb * 256 + t) * 8 + kc) * 8 + mtile) * 32 + lane) * 8;
        *reinterpret_cast<uint4*>(dst) = *reinterpret_cast<uint4*>(h2);
    }
}

// ---- head: 4-way split-K. 1024 blocks x 256 threads (z 0..63, kq 0..3), dual accumulators
__global__ __launch_bounds__(256) void vae_head_kernel(
    const float* __restrict__ eps,
    const float* __restrict__ Wm, const float* __restrict__ bm,
    const float* __restrict__ Wv, const float* __restrict__ bv,
    float* __restrict__ out)
{
    __shared__ float hs[HID];
    __shared__ float part[3][2][ZD];   // partials from kq = 1..3
    const int b   = blockIdx.x;
    const int tid = threadIdx.x;
    const int z   = tid & 63;
    const int kq  = tid >> 6;      // k-quarter 0..3
    // unpack this row's 512 h values from fragment layout
    {
        int mb = b >> 7, r = b & 127;
        int mtile = r >> 4, qid = r & 7, half = (r >> 3) & 1;
        for (int k = tid; k < HID; k += 256) {
            int kc = k >> 4, kin = k & 15;
            int khh = kin >> 3, qtr = (kin >> 1) & 3, u = kin & 1;
            size_t off = (((size_t)mb * 32 + kc) * 8 + mtile) * 256
                         + (size_t)(qid * 4 + qtr) * 8 + (half + 2 * khh) * 2 + u;
            hs[k] = __half2float(g_hp[off]);
        }
    }
    __syncthreads();
    const int k0 = kq * 128;
    float am0 = 0.0f, am1 = 0.0f, av0 = 0.0f, av1 = 0.0f;
#pragma unroll 8
    for (int k = 0; k < 128; k += 2) {
        float h0 = hs[k0 + k];
        float h1 = hs[k0 + k + 1];
        am0 = fmaf(h0, Wm[(size_t)(k0 + k) * ZD + z], am0);
        av0 = fmaf(h0, Wv[(size_t)(k0 + k) * ZD + z], av0);
        am1 = fmaf(h1, Wm[(size_t)(k0 + k + 1) * ZD + z], am1);
        av1 = fmaf(h1, Wv[(size_t)(k0 + k + 1) * ZD + z], av1);
    }
    float am = am0 + am1;
    float av = av0 + av1;
    if (kq > 0) {
        part[kq - 1][0][z] = am;
        part[kq - 1][1][z] = av;
    }
    __syncthreads();
    if (kq == 0) {
        am += part[0][0][z] + part[1][0][z] + part[2][0][z];
        av += part[0][1][z] + part[1][1][z] + part[2][1][z];
        float mu = am + bm[z];
        float lv = av + bv[z];
        size_t o = (size_t)b * ZD + z;
        out[o]                          = mu;
        out[(size_t)BATCH * ZD + o]     = lv;
        out[2 * (size_t)BATCH * ZD + o] = mu + eps[o] * __expf(0.5f * lv);
    }
}

extern "C" void kernel_launch(void* const* d_in, const int* in_sizes, int n_in,
                              void* d_out, int out_size)
{
    const float* x    = (const float*)d_in[0];
    const float* eps  = (const float*)d_in[1];
    const float* W    = (const float*)d_in[2];
    const float* U    = (const float*)d_in[3];
    const float* bias = (const float*)d_in[4];
    const float* Wm   = (const float*)d_in[5];
    const float* bm   = (const float*)d_in[6];
    const float* Wv   = (const float*)d_in[7];
    const float* bv   = (const float*)d_in[8];
    float* out = (float*)d_out;

    cudaFuncSetAttribute(lstm_persist_kernel,
                         cudaFuncAttributeMaxDynamicSharedMemorySize, SMEM_BYTES);

    pack_w_kernel<<<640, 256>>>(W, U);
    pack_x_kernel<<<dim3(256, 8), 256>>>(x);

    lstm_persist_kernel<<<dim3(16, 8), 512, SMEM_BYTES>>>(bias);

    vae_head_kernel<<<BATCH, 256>>>(eps, Wm, bm, Wv, bv, out);
}

// round 17
// speedup vs baseline: 1.0158x; 1.0158x over previous
#include <cuda_runtime.h>
#include <cuda_fp16.h>
#include <cstdint>

#define BATCH 1024
#define SEQT  256
#define DIN   128
#define HID   512
#define ZD    64
#define G4    2048   // 4*HID

// ---------------- packed fp16 operand buffers (mma.m16n8k16 fragment order) ----------------
// Weights: [hb(16)][kc(40)][wn(4)][gp(2)][lane(32)][8 halves]
__device__ __half g_wp[16 * 40 * 4 * 2 * 32 * 8];          // 2.62 MB
// x: [mb(8)][t(256)][kc(8)][mtile(8)][lane(32)][8 halves]
__device__ __half g_xp[8 * 256 * 8 * 8 * 32 * 8];          // 67 MB
// h ping-pong: [buf(2)][mb(8)][kc(32)][mtile(8)][lane(32)][8 halves]
__device__ __half g_hp[2 * 8 * 32 * 8 * 32 * 8];           // 2 MB
// per-mb barrier state (128B stride)
__device__ unsigned          g_bcnt[8 * 32];
__device__ volatile unsigned g_bgen[8 * 32];

__device__ __forceinline__ float sigmoidf_(float v) {
    return 1.0f / (1.0f + __expf(-v));
}
__device__ __forceinline__ float softplusf_(float v) {
    return (v > 20.0f) ? v : log1pf(__expf(v));
}
__device__ __forceinline__ void mma_f16(float c[4], const uint4& a, uint32_t b0, uint32_t b1) {
    asm volatile(
        "mma.sync.aligned.m16n8k16.row.col.f32.f16.f16.f32 "
        "{%0,%1,%2,%3}, {%4,%5,%6,%7}, {%8,%9}, {%0,%1,%2,%3};"
        : "+f"(c[0]), "+f"(c[1]), "+f"(c[2]), "+f"(c[3])
        : "r"(a.x), "r"(a.y), "r"(a.z), "r"(a.w), "r"(b0), "r"(b1));
}
// L1-cached 128-bit global load. Coherence across the per-step producer/consumer
// handoff is provided by the gpu-scope __threadfence() executed every step
// (emits CCTL.IVALL -> L1D invalidate) before these loads are issued.
__device__ __forceinline__ uint4 ldg_128(const void* p) {
    uint4 v;
    asm volatile("ld.global.v4.u32 {%0,%1,%2,%3}, [%4];"
                 : "=r"(v.x), "=r"(v.y), "=r"(v.z), "=r"(v.w) : "l"(p));
    return v;
}
__device__ __forceinline__ uint32_t h2_bits(__half2 h) {
    uint32_t u;
    memcpy(&u, &h, 4);
    return u;
}

constexpr int SMEM_BYTES = 40 * 4096;   // 160 KB: B slice [kc40][wn4][gp2][lane32][16B]

// ---- persistent kernel: grid (16 hb, 8 mb), 512 threads = 16 warps (4 wm x 4 wn)
__global__ __launch_bounds__(512, 1) void lstm_persist_kernel(const float* __restrict__ bias)
{
    extern __shared__ char sB[];
    const int hb  = blockIdx.x;
    const int mb  = blockIdx.y;
    const int tid = threadIdx.x;
    const int wid = tid >> 5;
    const int lane = tid & 31;
    const int wn = wid & 3;
    const int wm = wid >> 2;      // 0..3 -> mtiles {2wm, 2wm+1}
    const int qid = lane >> 2;
    const int qtr = lane & 3;

    // load persistent B slice into smem (once)
    {
        const uint4* src = reinterpret_cast<const uint4*>(g_wp) + (size_t)hb * (SMEM_BYTES / 16);
        uint4* dst = reinterpret_cast<uint4*>(sB);
        for (int i = tid; i < SMEM_BYTES / 16; i += 512) dst[i] = src[i];
    }
    float bs[4][2];
#pragma unroll
    for (int g = 0; g < 4; g++)
#pragma unroll
        for (int u = 0; u < 2; u++)
            bs[g][u] = bias[g * HID + hb * 32 + wn * 8 + qtr * 2 + u];

    float creg[2][2][2];
#pragma unroll
    for (int mt = 0; mt < 2; mt++)
#pragma unroll
        for (int h = 0; h < 2; h++)
#pragma unroll
            for (int u = 0; u < 2; u++)
                creg[mt][h][u] = 0.0f;

    float acc[2][4][4];

    auto zero_acc = [&]() {
#pragma unroll
        for (int mt = 0; mt < 2; mt++)
#pragma unroll
            for (int g = 0; g < 4; g++)
#pragma unroll
                for (int q = 0; q < 4; q++)
                    acc[mt][g][q] = 0.0f;
    };
    auto x_mma = [&](int tt) {
        const uint4* ax = reinterpret_cast<const uint4*>(
            g_xp + ((size_t)(mb * 256 + tt) * 8) * 2048);
#pragma unroll
        for (int kc = 0; kc < 8; kc++) {
            uint4 a0 = ax[(size_t)kc * 256 + (wm * 2 + 0) * 32 + lane];
            uint4 a1 = ax[(size_t)kc * 256 + (wm * 2 + 1) * 32 + lane];
            const uint4* bp = reinterpret_cast<const uint4*>(
                sB + kc * 4096 + (wn * 2) * 512 + lane * 16);
            uint4 b0 = bp[0];
            uint4 b1 = bp[32];
            mma_f16(acc[0][0], a0, b0.x, b0.y);
            mma_f16(acc[0][1], a0, b0.z, b0.w);
            mma_f16(acc[0][2], a0, b1.x, b1.y);
            mma_f16(acc[0][3], a0, b1.z, b1.w);
            mma_f16(acc[1][0], a1, b0.x, b0.y);
            mma_f16(acc[1][1], a1, b0.z, b0.w);
            mma_f16(acc[1][2], a1, b1.x, b1.y);
            mma_f16(acc[1][3], a1, b1.z, b1.w);
        }
    };

    __syncthreads();
    unsigned gen = g_bgen[mb * 32];

    const int kc_h  = hb * 2 + (wn >> 1);
    const int khalf = wn & 1;

    // prologue: x part of t=0 (h0 = 0)
    zero_acc();
    x_mma(0);

    for (int t = 0; t < SEQT; t++) {
        // ---- h chunks (kc 8..39): L1-cached loads (4 wn-warps share lines)
        if (t > 0) {
            const __half* ah = g_hp + ((size_t)((t & 1) * 8 + mb) * 32) * 2048;
#pragma unroll 8
            for (int kc = 0; kc < 32; kc++) {
                uint4 a0 = ldg_128(ah + ((size_t)kc * 8 + wm * 2 + 0) * 256 + lane * 8);
                uint4 a1 = ldg_128(ah + ((size_t)kc * 8 + wm * 2 + 1) * 256 + lane * 8);
                const uint4* bp = reinterpret_cast<const uint4*>(
                    sB + (kc + 8) * 4096 + (wn * 2) * 512 + lane * 16);
                uint4 b0 = bp[0];
                uint4 b1 = bp[32];
                mma_f16(acc[0][0], a0, b0.x, b0.y);
                mma_f16(acc[0][1], a0, b0.z, b0.w);
                mma_f16(acc[0][2], a0, b1.x, b1.y);
                mma_f16(acc[0][3], a0, b1.z, b1.w);
                mma_f16(acc[1][0], a1, b0.x, b0.y);
                mma_f16(acc[1][1], a1, b0.z, b0.w);
                mma_f16(acc[1][2], a1, b1.x, b1.y);
                mma_f16(acc[1][3], a1, b1.z, b1.w);
            }
        }

        // ---- LSTM epilogue: c in regs, h(t+1) written as packed fragments
        const int hbuf = (t + 1) & 1;
#pragma unroll
        for (int mt = 0; mt < 2; mt++) {
            float res[2][2];
#pragma unroll
            for (int half = 0; half < 2; half++) {
#pragma unroll
                for (int u = 0; u < 2; u++) {
                    int q = half * 2 + u;
                    float gi = acc[mt][0][q] + bs[0][u];
                    float gf = acc[mt][1][q] + bs[1][u];
                    float gg = acc[mt][2][q] + bs[2][u];
                    float go = acc[mt][3][q] + bs[3][u];
                    float iv = sigmoidf_(gi);
                    float fv = sigmoidf_(gf);
                    float gv = softplusf_(gg);
                    float ov = sigmoidf_(go);
                    float cn = fv * creg[mt][half][u] + iv * gv;
                    creg[mt][half][u] = cn;
                    res[half][u] = ov * softplusf_(cn);
                }
            }
            __half2 r0 = __floats2half2_rn(res[0][0], res[0][1]);
            __half2 r1 = __floats2half2_rn(res[1][0], res[1][1]);
            size_t off = (((size_t)(hbuf * 8 + mb) * 32 + kc_h) * 8 + (wm * 2 + mt)) * 256
                         + (size_t)(qid * 4 + qtr) * 8 + khalf * 4;
            uint2 val;
            val.x = h2_bits(r0);
            val.y = h2_bits(r1);
            *reinterpret_cast<uint2*>(g_hp + off) = val;
        }

        // ---- barrier with x-compute overlap
        if (t + 1 < SEQT) {
            __threadfence();
            __syncthreads();
            if (tid == 0) {
                unsigned ticket = atomicAdd(&g_bcnt[mb * 32], 1u);
                if (ticket == 15u) {
                    atomicExch(&g_bcnt[mb * 32], 0u);
                    __threadfence();
                    g_bgen[mb * 32] = gen + 1u;   // release immediately
                }
            }
            zero_acc();
            x_mma(t + 1);     // overlap: independent of other CTAs
            if (tid == 0) {
                while (g_bgen[mb * 32] == gen) __nanosleep(16);
            }
            __syncthreads();
            gen = gen + 1u;
            __threadfence();   // gpu-scope: CCTL.IVALL flushes L1D before next h reads
        }
    }
}

// ---- pack weights into fp16 fragment order
__global__ void pack_w_kernel(const float* __restrict__ W, const float* __restrict__ U) {
    int idx = blockIdx.x * blockDim.x + threadIdx.x;
    if (idx >= 16 * 40 * 4 * 2 * 32) return;
    int lane = idx & 31;
    int gp   = (idx >> 5) & 1;
    int wn   = (idx >> 6) & 3;
    int rest = idx >> 8;
    int kc = rest % 40;
    int hb = rest / 40;
    int qid = lane >> 2, qtr = lane & 3;
    __half2 h2[4];
#pragma unroll
    for (int g2 = 0; g2 < 2; g2++) {
        int col = (gp * 2 + g2) * HID + hb * 32 + wn * 8 + qid;
#pragma unroll
        for (int hi = 0; hi < 2; hi++) {
            int k = kc * 16 + qtr * 2 + hi * 8;
            float v0 = (k     < DIN) ? W[(size_t)k * G4 + col]       : U[(size_t)(k - DIN) * G4 + col];
            float v1 = (k + 1 < DIN) ? W[(size_t)(k + 1) * G4 + col] : U[(size_t)(k + 1 - DIN) * G4 + col];
            h2[g2 * 2 + hi] = __floats2half2_rn(v0, v1);
        }
    }
    __half* dst = g_wp + ((((size_t)(hb * 40 + kc) * 4 + wn) * 2 + gp) * 32 + lane) * 8;
    *reinterpret_cast<uint4*>(dst) = *reinterpret_cast<uint4*>(h2);
}

// ---- pack x via smem staging: block per (t, mb)
__global__ __launch_bounds__(256) void pack_x_kernel(const float* __restrict__ x) {
    __shared__ __half s[128 * 136];
    const int t  = blockIdx.x;
    const int mb = blockIdx.y;
    const int tid = threadIdx.x;
    for (int i = tid; i < 128 * 32; i += 256) {
        int row = i >> 5, q4 = i & 31;
        const float4 v = *reinterpret_cast<const float4*>(
            x + ((size_t)(mb * 128 + row) * SEQT + t) * DIN + q4 * 4);
        __half2 lo = __floats2half2_rn(v.x, v.y);
        __half2 hi = __floats2half2_rn(v.z, v.w);
        __half* p = s + row * 136 + q4 * 4;
        *reinterpret_cast<__half2*>(p)     = lo;
        *reinterpret_cast<__half2*>(p + 2) = hi;
    }
    __syncthreads();
    for (int o = tid; o < 2048; o += 256) {
        int lane = o & 31, mtile = (o >> 5) & 7, kc = o >> 8;
        int qid = lane >> 2, qtr = lane & 3;
        int row0 = mtile * 16 + qid;
        int k0 = kc * 16 + qtr * 2;
        __half2 h2[4];
        h2[0] = *reinterpret_cast<const __half2*>(s + row0 * 136 + k0);
        h2[1] = *reinterpret_cast<const __half2*>(s + (row0 + 8) * 136 + k0);
        h2[2] = *reinterpret_cast<const __half2*>(s + row0 * 136 + k0 + 8);
        h2[3] = *reinterpret_cast<const __half2*>(s + (row0 + 8) * 136 + k0 + 8);
        __half* dst = g_xp + ((((size_t)(mb * 256 + t) * 8 + kc) * 8 + mtile) * 32 + lane) * 8;
        *reinterpret_cast<uint4*>(dst) = *reinterpret_cast<uint4*>(h2);
    }
}

// ---- head: 4-way split-K. 1024 blocks x 256 threads (z 0..63, kq 0..3), dual accumulators
__global__ __launch_bounds__(256) void vae_head_kernel(
    const float* __restrict__ eps,
    const float* __restrict__ Wm, const float* __restrict__ bm,
    const float* __restrict__ Wv, const float* __restrict__ bv,
    float* __restrict__ out)
{
    __shared__ float hs[HID];
    __shared__ float part[3][2][ZD];   // partials from kq = 1..3
    const int b   = blockIdx.x;
    const int tid = threadIdx.x;
    const int z   = tid & 63;
    const int kq  = tid >> 6;      // k-quarter 0..3
    {
        int mb = b >> 7, r = b & 127;
        int mtile = r >> 4, qid = r & 7, half = (r >> 3) & 1;
        for (int k = tid; k < HID; k += 256) {
            int kc = k >> 4, kin = k & 15;
            int khh = kin >> 3, qtr = (kin >> 1) & 3, u = kin & 1;
            size_t off = (((size_t)mb * 32 + kc) * 8 + mtile) * 256
                         + (size_t)(qid * 4 + qtr) * 8 + (half + 2 * khh) * 2 + u;
            hs[k] = __half2float(g_hp[off]);
        }
    }
    __syncthreads();
    const int k0 = kq * 128;
    float am0 = 0.0f, am1 = 0.0f, av0 = 0.0f, av1 = 0.0f;
#pragma unroll 8
    for (int k = 0; k < 128; k += 2) {
        float h0 = hs[k0 + k];
        float h1 = hs[k0 + k + 1];
        am0 = fmaf(h0, Wm[(size_t)(k0 + k) * ZD + z], am0);
        av0 = fmaf(h0, Wv[(size_t)(k0 + k) * ZD + z], av0);
        am1 = fmaf(h1, Wm[(size_t)(k0 + k + 1) * ZD + z], am1);
        av1 = fmaf(h1, Wv[(size_t)(k0 + k + 1) * ZD + z], av1);
    }
    float am = am0 + am1;
    float av = av0 + av1;
    if (kq > 0) {
        part[kq - 1][0][z] = am;
        part[kq - 1][1][z] = av;
    }
    __syncthreads();
    if (kq == 0) {
        am += part[0][0][z] + part[1][0][z] + part[2][0][z];
        av += part[0][1][z] + part[1][1][z] + part[2][1][z];
        float mu = am + bm[z];
        float lv = av + bv[z];
        size_t o = (size_t)b * ZD + z;
        out[o]                          = mu;
        out[(size_t)BATCH * ZD + o]     = lv;
        out[2 * (size_t)BATCH * ZD + o] = mu + eps[o] * __expf(0.5f * lv);
    }
}

extern "C" void kernel_launch(void* const* d_in, const int* in_sizes, int n_in,
                              void* d_out, int out_size)
{
    const float* x    = (const float*)d_in[0];
    const float* eps  = (const float*)d_in[1];
    const float* W    = (const float*)d_in[2];
    const float* U    = (const float*)d_in[3];
    const float* bias = (const float*)d_in[4];
    const float* Wm   = (const float*)d_in[5];
    const float* bm   = (const float*)d_in[6];
    const float* Wv   = (const float*)d_in[7];
    const float* bv   = (const float*)d_in[8];
    float* out = (float*)d_out;

    cudaFuncSetAttribute(lstm_persist_kernel,
                         cudaFuncAttributeMaxDynamicSharedMemorySize, SMEM_BYTES);

    pack_w_kernel<<<640, 256>>>(W, U);
    pack_x_kernel<<<dim3(256, 8), 256>>>(x);

    lstm_persist_kernel<<<dim3(16, 8), 512, SMEM_BYTES>>>(bias);

    vae_head_kernel<<<BATCH, 256>>>(eps, Wm, bm, Wv, bv, out);
}